// round 16
// baseline (speedup 1.0000x reference)
#include <cuda_runtime.h>
#include <cuda_bf16.h>
#include <cstdint>
#include <math.h>

#define B_  32
#define C_  512
#define HW  1024
#define EPS 1e-5f

typedef __nv_bfloat16 bf16;

// ---------------------------------------------------------------------------
// Scratch (__device__ globals; allocation-free rule)
// ---------------------------------------------------------------------------
__device__ __align__(128) bf16  g_hnT[(size_t)B_ * HW * C_];    // [b, p, c]
__device__ __align__(128) bf16  g_qkT[(size_t)B_ * HW * 1024];  // [b, p, q|k]
__device__ __align__(128) bf16  g_v  [(size_t)B_ * C_ * HW];    // [b, c, p]
__device__ __align__(128) bf16  g_oT [(size_t)B_ * HW * C_];    // [b, p, c]
__device__ __align__(128) bf16  g_probs[(size_t)B_ * HW * HW];  // bf16 exp(s)
__device__ __align__(128) bf16  g_w[4][C_ * C_];                // wq,wk,wv,wp bf16
__device__ float  g_bqk[1024];                                  // bq|bk packed
__device__ float  g_rowsum[(size_t)B_ * HW];                    // softmax denominators

// ---------------------------------------------------------------------------
// Helpers
// ---------------------------------------------------------------------------
__device__ __forceinline__ uint32_t smem_u32(const void* p) {
    uint32_t a;
    asm("{ .reg .u64 t; cvta.to.shared.u64 t, %1; cvt.u32.u64 %0, t; }" : "=r"(a) : "l"(p));
    return a;
}
__device__ __forceinline__ void cp16(uint32_t s, const void* g) {
    asm volatile("cp.async.cg.shared.global [%0], [%1], 16;" :: "r"(s), "l"(g));
}
__device__ __forceinline__ void ldsm4(uint32_t* r, uint32_t a) {
    asm volatile("ldmatrix.sync.aligned.m8n8.x4.shared.b16 {%0,%1,%2,%3}, [%4];"
                 : "=r"(r[0]), "=r"(r[1]), "=r"(r[2]), "=r"(r[3]) : "r"(a));
}
__device__ __forceinline__ void mma16(float* d, const uint32_t* a, uint32_t b0, uint32_t b1) {
    asm volatile("mma.sync.aligned.m16n8k16.row.col.f32.bf16.bf16.f32 "
        "{%0,%1,%2,%3}, {%4,%5,%6,%7}, {%8,%9}, {%0,%1,%2,%3};"
        : "+f"(d[0]), "+f"(d[1]), "+f"(d[2]), "+f"(d[3])
        : "r"(a[0]), "r"(a[1]), "r"(a[2]), "r"(a[3]), "r"(b0), "r"(b1));
}

// ---------------------------------------------------------------------------
// GEMM core (device function): D[m,n] = alpha * sum_k A[m,k]*B[n,k]
// (+bias) (+R) (EXP: exp + row-sum atomics) (DIV: /rowsum).
// CTA tile 128x128x32, 128 threads, warp tile 64x64, 5-stage cp.async ring,
// register fragment double buffering. K-tile order rotated per CTA parity
// so co-resident CTAs de-phase their sync/load bursts.
// ---------------------------------------------------------------------------
#define BM 128
#define BN 128
#define BKB 32
#define ROWB 80
#define STAGE_B (BM * ROWB)            // 10240 bytes per operand stage
#define NSTAGE 5
#define GEMM_SMEM (2 * NSTAGE * STAGE_B)   // 102400 bytes

template<bool BIAS_M, bool BIAS_N, bool RES, bool OUTBF, bool EXP, bool DIV>
__device__ __forceinline__ void gemm_core(
    const bf16* __restrict__ A, const bf16* __restrict__ Bm, void* __restrict__ Cp,
    const float* __restrict__ bias, const float* __restrict__ R,
    float* __restrict__ rsums,
    int M, int N, int K, int lda, int ldb,
    size_t sA, size_t sB, size_t sC, size_t sR, float alpha,
    int m0, int n0, int bz, int rot, char* smem)
{
    uint32_t su = smem_u32(smem);
    const uint32_t BOFF = NSTAGE * STAGE_B;

    int tid = threadIdx.x, lane = tid & 31, wid = tid >> 5;
    A += sA * bz; Bm += sB * bz;
    if (RES) R += sR * bz;
    if (EXP || DIV) rsums += (size_t)bz * M;

    int wm = (wid & 1) * 64;
    int wn = (wid >> 1) * 64;
    int g = lane >> 2, c = lane & 3;

    int a_row = (lane & 7) + ((lane >> 3) & 1) * 8;
    int a_kh  = lane >> 4;
    uint32_t aoff = (uint32_t)((wm + a_row) * ROWB + a_kh * 16);
    int b_row = (lane & 7) + ((lane >> 4) & 1) * 8;
    int b_kh  = (lane >> 3) & 1;
    uint32_t boffb = (uint32_t)((wn + b_row) * ROWB + b_kh * 16);

    float acc[4][8][4];
    #pragma unroll
    for (int mt = 0; mt < 4; mt++)
        #pragma unroll
        for (int nt = 0; nt < 8; nt++)
            #pragma unroll
            for (int r_ = 0; r_ < 4; r_++) acc[mt][nt][r_] = 0.f;

    const int KT = K / BKB;
    int lrow = tid >> 2, lch = tid & 3;
    // load logical tile kt (physical tile (kt+rot)%KT) into stage st
    auto load_tile = [&](int kt, int st) {
        int kp = kt + rot; if (kp >= KT) kp -= KT;
        const bf16* Ag = A  + (size_t)m0 * lda + kp * BKB;
        const bf16* Bg = Bm + (size_t)n0 * ldb + kp * BKB;
        uint32_t so = su + (uint32_t)st * STAGE_B;
        #pragma unroll
        for (int i = 0; i < 4; i++) {
            int row = lrow + i * 32;
            uint32_t off = (uint32_t)(row * ROWB + lch * 16);
            cp16(so + off,        Ag + (size_t)row * lda + lch * 8);
            cp16(so + BOFF + off, Bg + (size_t)row * ldb + lch * 8);
        }
        asm volatile("cp.async.commit_group;" ::: "memory");
    };

    uint32_t af[2][4][4], bfr[2][4][4];
    auto ldsm_slab = [&](int st, int sl, int buf) {
        uint32_t abase = su + (uint32_t)st * STAGE_B;
        uint32_t bbase = abase + BOFF;
        uint32_t ko = (uint32_t)sl * 32;
        #pragma unroll
        for (int mt = 0; mt < 4; mt++)
            ldsm4(af[buf][mt], abase + aoff + mt * (16 * ROWB) + ko);
        #pragma unroll
        for (int pr = 0; pr < 4; pr++)
            ldsm4(bfr[buf][pr], bbase + boffb + pr * (16 * ROWB) + ko);
    };
    auto mma_slab = [&](int buf) {
        #pragma unroll
        for (int pr = 0; pr < 4; pr++)
            #pragma unroll
            for (int mt = 0; mt < 4; mt++) {
                mma16(acc[mt][pr * 2 + 0], af[buf][mt], bfr[buf][pr][0], bfr[buf][pr][1]);
                mma16(acc[mt][pr * 2 + 1], af[buf][mt], bfr[buf][pr][2], bfr[buf][pr][3]);
            }
    };

    load_tile(0, 0); load_tile(1, 1); load_tile(2, 2); load_tile(3, 3);
    asm volatile("cp.async.wait_group 3;" ::: "memory");
    __syncthreads();
    ldsm_slab(0, 0, 0);

    for (int kt = 0; kt < KT; kt++) {
        int cur = kt % NSTAGE;
        ldsm_slab(cur, 1, 1);
        mma_slab(0);
        if (kt + 4 < KT) load_tile(kt + 4, (kt + 4) % NSTAGE);
        if (kt + 1 < KT) {
            if (kt + 4 < KT)      asm volatile("cp.async.wait_group 3;" ::: "memory");
            else if (kt + 3 < KT) asm volatile("cp.async.wait_group 2;" ::: "memory");
            else if (kt + 2 < KT) asm volatile("cp.async.wait_group 1;" ::: "memory");
            else                  asm volatile("cp.async.wait_group 0;" ::: "memory");
            __syncthreads();
            ldsm_slab((kt + 1) % NSTAGE, 0, 0);
        }
        mma_slab(1);
    }

    #pragma unroll
    for (int mt = 0; mt < 4; mt++) {
        #pragma unroll
        for (int half = 0; half < 2; half++) {
            int m = m0 + wm + mt * 16 + g + half * 8;
            float bm = BIAS_M ? bias[m] : 0.f;
            float dm = DIV ? (1.f / rsums[m]) : 1.f;
            float rsum = 0.f;
            #pragma unroll
            for (int nt = 0; nt < 8; nt++) {
                int n = n0 + wn + nt * 8 + c * 2;
                float v0 = acc[mt][nt][half * 2 + 0] * alpha + bm;
                float v1 = acc[mt][nt][half * 2 + 1] * alpha + bm;
                if (BIAS_N) { v0 += bias[n]; v1 += bias[n + 1]; }
                if (EXP) { v0 = __expf(v0); v1 = __expf(v1); rsum += v0 + v1; }
                if (DIV) { v0 *= dm; v1 *= dm; }
                size_t off = (size_t)m * N + n;
                if (RES) { v0 += R[off]; v1 += R[off + 1]; }
                if (OUTBF) {
                    *(__nv_bfloat162*)((bf16*)Cp + sC * bz + off) = __floats2bfloat162_rn(v0, v1);
                } else {
                    *(float2*)((float*)Cp + sC * bz + off) = make_float2(v0, v1);
                }
            }
            if (EXP) {
                rsum += __shfl_xor_sync(0xFFFFFFFFu, rsum, 1);
                rsum += __shfl_xor_sync(0xFFFFFFFFu, rsum, 2);
                if (c == 0) atomicAdd(&rsums[m], rsum);
            }
        }
    }
}

// Standalone GEMM wrapper (S, PV, proj)
template<bool BIAS_M, bool BIAS_N, bool RES, bool OUTBF, bool EXP, bool DIV>
__global__ __launch_bounds__(128, 2) void gemm_bf(
    const bf16* __restrict__ A, const bf16* __restrict__ Bm, void* __restrict__ Cp,
    const float* __restrict__ bias, const float* __restrict__ R,
    float* __restrict__ rsums,
    int M, int N, int K, int lda, int ldb,
    size_t sA, size_t sB, size_t sC, size_t sR, float alpha)
{
    extern __shared__ char smem[];
    int rot = ((blockIdx.x ^ blockIdx.y ^ blockIdx.z) & 1) ? (K / BKB / 2) : 0;
    gemm_core<BIAS_M, BIAS_N, RES, OUTBF, EXP, DIV>(
        A, Bm, Cp, bias, R, rsums, M, N, K, lda, ldb, sA, sB, sC, sR, alpha,
        blockIdx.y * BM, blockIdx.x * BN, blockIdx.z, rot, smem);
}

// Merged qk + V launch: blockIdx.y in [0,8) -> qk rows; [8,12) -> V rows.
__global__ __launch_bounds__(128, 2) void qkv_kernel(
    const bf16* __restrict__ hnT, const bf16* __restrict__ wqk,
    const bf16* __restrict__ wv, bf16* __restrict__ qkT, bf16* __restrict__ v,
    const float* __restrict__ bqk, const float* __restrict__ bv,
    size_t sCH, size_t sQK)
{
    extern __shared__ char smem[];
    int rot = ((blockIdx.x ^ blockIdx.y ^ blockIdx.z) & 1) ? (512 / BKB / 2) : 0;
    if (blockIdx.y < 8) {
        gemm_core<false, true, false, true, false, false>(
            hnT, wqk, qkT, bqk, nullptr, nullptr,
            1024, 1024, 512, 512, 512, sCH, 0, sQK, 0, 1.f,
            blockIdx.y * BM, blockIdx.x * BN, blockIdx.z, rot, smem);
    } else {
        gemm_core<true, false, false, true, false, false>(
            wv, hnT, v, bv, nullptr, nullptr,
            512, 1024, 512, 512, 512, 0, sCH, sCH, 0, 1.f,
            (blockIdx.y - 8) * BM, blockIdx.x * BN, blockIdx.z, rot, smem);
    }
}

// ---------------------------------------------------------------------------
// Merged prep: blocks [0,1024): fused GroupNorm (stats+normalize+transpose);
// blocks [1024,2048): weight cvt (+bias pack); blocks [2048,2176): zero rsums.
// ---------------------------------------------------------------------------
#define GN_SMEM (16 * HW * 4)   // 65536 bytes

__global__ __launch_bounds__(256) void prep_kernel(
    const float* __restrict__ x, const float* __restrict__ scale,
    const float* __restrict__ bias, bf16* __restrict__ hnT,
    const float* __restrict__ w0, const float* __restrict__ w1,
    const float* __restrict__ w2, const float* __restrict__ w3,
    const float* __restrict__ bq, const float* __restrict__ bk,
    bf16* __restrict__ wdst, float* __restrict__ bqk, float* __restrict__ rsums)
{
    int bid = blockIdx.x, tid = threadIdx.x;

    if (bid >= 2048) {                       // zero rsums: 128 blocks x 1024 floats
        int i = (bid - 2048) * 256 + tid;
        ((float4*)rsums)[i] = make_float4(0.f, 0.f, 0.f, 0.f);
        return;
    }
    if (bid >= 1024) {                       // weight cvt: 1024 blocks
        int cb = bid - 1024;
        int wy = cb >> 8, wx = cb & 255;
        const float* src = (wy == 0) ? w0 : (wy == 1) ? w1 : (wy == 2) ? w2 : w3;
        bf16* d = wdst + (size_t)wy * C_ * C_;
        int i = wx * 256 + tid;
        float4 vv = *(const float4*)(src + i * 4);
        __nv_bfloat162* d2 = (__nv_bfloat162*)(d + i * 4);
        d2[0] = __floats2bfloat162_rn(vv.x, vv.y);
        d2[1] = __floats2bfloat162_rn(vv.z, vv.w);
        if (wy == 0 && wx < 2) {
            int j = wx * 256 + tid;
            bqk[j] = bq[j]; bqk[j + 512] = bk[j];
        }
        return;
    }

    // fused GroupNorm
    extern __shared__ float xs[];                 // [16][1024]
    __shared__ float red_s[8], red_ss[8];
    __shared__ float a_sh[16], ad_sh[16];

    int lane = tid & 31, warp = tid >> 5;
    int b = bid >> 5, g = bid & 31;
    int c0 = g * 16;
    size_t base = ((size_t)b * C_ + c0) * HW;

    const float4* x4 = (const float4*)(x + base);
    float4* xs4 = (float4*)xs;
    float s = 0.f, ss = 0.f;
    #pragma unroll
    for (int i = tid; i < 4096; i += 256) {
        float4 vv = x4[i];
        xs4[i] = vv;
        s  += vv.x + vv.y + vv.z + vv.w;
        ss += vv.x * vv.x + vv.y * vv.y + vv.z * vv.z + vv.w * vv.w;
    }
    #pragma unroll
    for (int o = 16; o > 0; o >>= 1) {
        s  += __shfl_xor_sync(0xFFFFFFFFu, s, o);
        ss += __shfl_xor_sync(0xFFFFFFFFu, ss, o);
    }
    if (lane == 0) { red_s[warp] = s; red_ss[warp] = ss; }
    __syncthreads();
    if (tid < 16) {
        float ts = 0.f, tss = 0.f;
        #pragma unroll
        for (int w = 0; w < 8; w++) { ts += red_s[w]; tss += red_ss[w]; }
        float mean = ts * (1.f / 16384.f);
        float var  = tss * (1.f / 16384.f) - mean * mean;
        float inv  = rsqrtf(var + EPS);
        float a    = scale[c0 + tid] * inv;
        a_sh[tid]  = a;
        ad_sh[tid] = bias[c0 + tid] - mean * a;
    }
    __syncthreads();

    float a[16], ad[16];
    #pragma unroll
    for (int c = 0; c < 16; c++) { a[c] = a_sh[c]; ad[c] = ad_sh[c]; }

    #pragma unroll
    for (int i = 0; i < 4; i++) {
        int p = tid + i * 256;
        uint32_t pk[8];
        #pragma unroll
        for (int c = 0; c < 8; c++) {
            float v0 = xs[(2 * c + 0) * HW + p] * a[2 * c + 0] + ad[2 * c + 0];
            float v1 = xs[(2 * c + 1) * HW + p] * a[2 * c + 1] + ad[2 * c + 1];
            __nv_bfloat162 h = __floats2bfloat162_rn(v0, v1);
            pk[c] = *(uint32_t*)&h;
        }
        uint4* dst = (uint4*)(hnT + ((size_t)b * HW + p) * C_ + c0);
        dst[0] = make_uint4(pk[0], pk[1], pk[2], pk[3]);
        dst[1] = make_uint4(pk[4], pk[5], pk[6], pk[7]);
    }
}

// ---------------------------------------------------------------------------
extern "C" void kernel_launch(void* const* d_in, const int* in_sizes, int n_in,
                              void* d_out, int out_size)
{
    const float* x  = (const float*)d_in[0];
    const float* gs = (const float*)d_in[1];
    const float* gb = (const float*)d_in[2];
    const float* wq = (const float*)d_in[3];
    const float* bq = (const float*)d_in[4];
    const float* wk = (const float*)d_in[5];
    const float* bk = (const float*)d_in[6];
    const float* wv = (const float*)d_in[7];
    const float* bv = (const float*)d_in[8];
    const float* wp = (const float*)d_in[9];
    const float* bp = (const float*)d_in[10];
    float* out = (float*)d_out;

    bf16 *hnT, *qkT, *v, *oT, *probs, *wb; float *bqk, *rsums;
    cudaGetSymbolAddress((void**)&hnT,   g_hnT);
    cudaGetSymbolAddress((void**)&qkT,   g_qkT);
    cudaGetSymbolAddress((void**)&v,     g_v);
    cudaGetSymbolAddress((void**)&oT,    g_oT);
    cudaGetSymbolAddress((void**)&probs, g_probs);
    cudaGetSymbolAddress((void**)&wb,    g_w);
    cudaGetSymbolAddress((void**)&bqk,   g_bqk);
    cudaGetSymbolAddress((void**)&rsums, g_rowsum);
    bf16 *wvb = wb + 2 * C_ * C_, *wpb = wb + 3 * C_ * C_;

    cudaFuncSetAttribute(prep_kernel, cudaFuncAttributeMaxDynamicSharedMemorySize, GN_SMEM);
    cudaFuncSetAttribute(qkv_kernel,  cudaFuncAttributeMaxDynamicSharedMemorySize, GEMM_SMEM);
    cudaFuncSetAttribute(gemm_bf<false, false, false, true,  true,  false>, cudaFuncAttributeMaxDynamicSharedMemorySize, GEMM_SMEM);
    cudaFuncSetAttribute(gemm_bf<false, false, false, true,  false, true >, cudaFuncAttributeMaxDynamicSharedMemorySize, GEMM_SMEM);
    cudaFuncSetAttribute(gemm_bf<true,  false, true,  false, false, false>, cudaFuncAttributeMaxDynamicSharedMemorySize, GEMM_SMEM);

    const size_t sCH = (size_t)C_ * HW;     // 512*1024
    const size_t sQK = (size_t)HW * 1024;   // qkT batch stride
    const size_t sAA = (size_t)HW * HW;
    const float  scl = 1.f / sqrtf((float)C_);

    // 1) prep: GroupNorm + weight cvt + rsums zero (one launch)
    prep_kernel<<<2176, 256, GN_SMEM>>>(x, gs, gb, hnT,
                                        wq, wk, wv, wp, bq, bk, wb, bqk, rsums);

    // 2) merged qk + V GEMMs (one launch)
    qkv_kernel<<<dim3(8, 12, B_), 128, GEMM_SMEM>>>(hnT, wb, wvb, qkT, v, bqk, bv, sCH, sQK);

    // 3) probs = exp(scl * Q @ K^T) (bf16, unnormalized) + row sums via atomics
    {
        dim3 g(1024 / BN, 1024 / BM, B_);
        gemm_bf<false, false, false, true, true, false><<<g, 128, GEMM_SMEM>>>(
            qkT, qkT + 512, probs, nullptr, nullptr, rsums,
            1024, 1024, 512, 1024, 1024, sQK, sQK, sAA, 0, scl);
    }
    // 4) OT[i,co] = (probs @ V^T) / rowsum[i]   (M=1024, N=512, K=1024)
    {
        dim3 g(512 / BN, 1024 / BM, B_);
        gemm_bf<false, false, false, true, false, true><<<g, 128, GEMM_SMEM>>>(
            probs, v, oT, nullptr, nullptr, rsums,
            1024, 512, 1024, 1024, 1024, sAA, sCH, sCH, 0, 1.f);
    }
    // 5) out[co,p] = wp @ OT^T + bp + x    (M=512, N=1024, K=512) -> fp32 + residual
    {
        dim3 g(1024 / BN, 512 / BM, B_);
        gemm_bf<true, false, true, false, false, false><<<g, 128, GEMM_SMEM>>>(
            wpb, oT, out, bp, x, nullptr,
            512, 1024, 512, 512, 512, 0, sCH, sCH, sCH, 1.f);
    }
}

// round 17
// speedup vs baseline: 1.0090x; 1.0090x over previous
#include <cuda_runtime.h>
#include <cuda_bf16.h>
#include <cstdint>
#include <math.h>

#define B_  32
#define C_  512
#define HW  1024
#define EPS 1e-5f

typedef __nv_bfloat16 bf16;

// ---------------------------------------------------------------------------
// Scratch (__device__ globals; allocation-free rule)
// ---------------------------------------------------------------------------
__device__ __align__(128) bf16  g_hnT[(size_t)B_ * HW * C_];    // [b, p, c]
__device__ __align__(128) bf16  g_qkT[(size_t)B_ * HW * 1024];  // [b, p, q|k]
__device__ __align__(128) bf16  g_v  [(size_t)B_ * C_ * HW];    // [b, c, p]
__device__ __align__(128) bf16  g_oT [(size_t)B_ * HW * C_];    // [b, p, c]
__device__ __align__(128) bf16  g_probs[(size_t)B_ * HW * HW];  // bf16 exp(s)
__device__ __align__(128) bf16  g_w[4][C_ * C_];                // wq,wk,wv,wp bf16
__device__ float  g_bqk[1024];                                  // bq|bk packed
__device__ float  g_rowsum[(size_t)B_ * HW];                    // softmax denominators

// ---------------------------------------------------------------------------
// Helpers
// ---------------------------------------------------------------------------
__device__ __forceinline__ uint32_t smem_u32(const void* p) {
    uint32_t a;
    asm("{ .reg .u64 t; cvta.to.shared.u64 t, %1; cvt.u32.u64 %0, t; }" : "=r"(a) : "l"(p));
    return a;
}
__device__ __forceinline__ void cp16(uint32_t s, const void* g) {
    asm volatile("cp.async.cg.shared.global [%0], [%1], 16;" :: "r"(s), "l"(g));
}
__device__ __forceinline__ void ldsm4(uint32_t* r, uint32_t a) {
    asm volatile("ldmatrix.sync.aligned.m8n8.x4.shared.b16 {%0,%1,%2,%3}, [%4];"
                 : "=r"(r[0]), "=r"(r[1]), "=r"(r[2]), "=r"(r[3]) : "r"(a));
}
__device__ __forceinline__ void mma16(float* d, const uint32_t* a, uint32_t b0, uint32_t b1) {
    asm volatile("mma.sync.aligned.m16n8k16.row.col.f32.bf16.bf16.f32 "
        "{%0,%1,%2,%3}, {%4,%5,%6,%7}, {%8,%9}, {%0,%1,%2,%3};"
        : "+f"(d[0]), "+f"(d[1]), "+f"(d[2]), "+f"(d[3])
        : "r"(a[0]), "r"(a[1]), "r"(a[2]), "r"(a[3]), "r"(b0), "r"(b1));
}

// ---------------------------------------------------------------------------
// GEMM core (device function): D[m,n] = alpha * sum_k A[m,k]*B[n,k]
// (+bias) (+R) (EXP: exp + row-sum atomics) (DIV: /rowsum).
// CTA tile 128x128x32, 128 threads, warp tile 64x64, 5-stage cp.async ring,
// register fragment double buffering.
// ---------------------------------------------------------------------------
#define BM 128
#define BN 128
#define BKB 32
#define ROWB 80
#define STAGE_B (BM * ROWB)            // 10240 bytes per operand stage
#define NSTAGE 5
#define GEMM_SMEM (2 * NSTAGE * STAGE_B)   // 102400 bytes

template<bool BIAS_M, bool BIAS_N, bool RES, bool OUTBF, bool EXP, bool DIV>
__device__ __forceinline__ void gemm_core(
    const bf16* __restrict__ A, const bf16* __restrict__ Bm, void* __restrict__ Cp,
    const float* __restrict__ bias, const float* __restrict__ R,
    float* __restrict__ rsums,
    int M, int N, int K, int lda, int ldb,
    size_t sA, size_t sB, size_t sC, size_t sR, float alpha,
    int m0, int n0, int bz, char* smem)
{
    uint32_t su = smem_u32(smem);
    const uint32_t BOFF = NSTAGE * STAGE_B;

    int tid = threadIdx.x, lane = tid & 31, wid = tid >> 5;
    A += sA * bz; Bm += sB * bz;
    if (RES) R += sR * bz;
    if (EXP || DIV) rsums += (size_t)bz * M;

    int wm = (wid & 1) * 64;
    int wn = (wid >> 1) * 64;
    int g = lane >> 2, c = lane & 3;

    int a_row = (lane & 7) + ((lane >> 3) & 1) * 8;
    int a_kh  = lane >> 4;
    uint32_t aoff = (uint32_t)((wm + a_row) * ROWB + a_kh * 16);
    int b_row = (lane & 7) + ((lane >> 4) & 1) * 8;
    int b_kh  = (lane >> 3) & 1;
    uint32_t boffb = (uint32_t)((wn + b_row) * ROWB + b_kh * 16);

    float acc[4][8][4];
    #pragma unroll
    for (int mt = 0; mt < 4; mt++)
        #pragma unroll
        for (int nt = 0; nt < 8; nt++)
            #pragma unroll
            for (int r_ = 0; r_ < 4; r_++) acc[mt][nt][r_] = 0.f;

    int lrow = tid >> 2, lch = tid & 3;
    auto load_tile = [&](int kt, int st) {
        const bf16* Ag = A  + (size_t)m0 * lda + kt * BKB;
        const bf16* Bg = Bm + (size_t)n0 * ldb + kt * BKB;
        uint32_t so = su + (uint32_t)st * STAGE_B;
        #pragma unroll
        for (int i = 0; i < 4; i++) {
            int row = lrow + i * 32;
            uint32_t off = (uint32_t)(row * ROWB + lch * 16);
            cp16(so + off,        Ag + (size_t)row * lda + lch * 8);
            cp16(so + BOFF + off, Bg + (size_t)row * ldb + lch * 8);
        }
        asm volatile("cp.async.commit_group;" ::: "memory");
    };

    uint32_t af[2][4][4], bfr[2][4][4];
    auto ldsm_slab = [&](int st, int sl, int buf) {
        uint32_t abase = su + (uint32_t)st * STAGE_B;
        uint32_t bbase = abase + BOFF;
        uint32_t ko = (uint32_t)sl * 32;
        #pragma unroll
        for (int mt = 0; mt < 4; mt++)
            ldsm4(af[buf][mt], abase + aoff + mt * (16 * ROWB) + ko);
        #pragma unroll
        for (int pr = 0; pr < 4; pr++)
            ldsm4(bfr[buf][pr], bbase + boffb + pr * (16 * ROWB) + ko);
    };
    auto mma_slab = [&](int buf) {
        #pragma unroll
        for (int pr = 0; pr < 4; pr++)
            #pragma unroll
            for (int mt = 0; mt < 4; mt++) {
                mma16(acc[mt][pr * 2 + 0], af[buf][mt], bfr[buf][pr][0], bfr[buf][pr][1]);
                mma16(acc[mt][pr * 2 + 1], af[buf][mt], bfr[buf][pr][2], bfr[buf][pr][3]);
            }
    };

    load_tile(0, 0); load_tile(1, 1); load_tile(2, 2); load_tile(3, 3);
    asm volatile("cp.async.wait_group 3;" ::: "memory");
    __syncthreads();
    ldsm_slab(0, 0, 0);

    const int KT = K / BKB;
    for (int kt = 0; kt < KT; kt++) {
        int cur = kt % NSTAGE;
        ldsm_slab(cur, 1, 1);
        mma_slab(0);
        if (kt + 4 < KT) load_tile(kt + 4, (kt + 4) % NSTAGE);
        if (kt + 1 < KT) {
            if (kt + 4 < KT)      asm volatile("cp.async.wait_group 3;" ::: "memory");
            else if (kt + 3 < KT) asm volatile("cp.async.wait_group 2;" ::: "memory");
            else if (kt + 2 < KT) asm volatile("cp.async.wait_group 1;" ::: "memory");
            else                  asm volatile("cp.async.wait_group 0;" ::: "memory");
            __syncthreads();
            ldsm_slab((kt + 1) % NSTAGE, 0, 0);
        }
        mma_slab(1);
    }

    #pragma unroll
    for (int mt = 0; mt < 4; mt++) {
        #pragma unroll
        for (int half = 0; half < 2; half++) {
            int m = m0 + wm + mt * 16 + g + half * 8;
            float bm = BIAS_M ? bias[m] : 0.f;
            float dm = DIV ? (1.f / rsums[m]) : 1.f;
            float rsum = 0.f;
            #pragma unroll
            for (int nt = 0; nt < 8; nt++) {
                int n = n0 + wn + nt * 8 + c * 2;
                float v0 = acc[mt][nt][half * 2 + 0] * alpha + bm;
                float v1 = acc[mt][nt][half * 2 + 1] * alpha + bm;
                if (BIAS_N) { v0 += bias[n]; v1 += bias[n + 1]; }
                if (EXP) { v0 = __expf(v0); v1 = __expf(v1); rsum += v0 + v1; }
                if (DIV) { v0 *= dm; v1 *= dm; }
                size_t off = (size_t)m * N + n;
                if (RES) { v0 += R[off]; v1 += R[off + 1]; }
                if (OUTBF) {
                    *(__nv_bfloat162*)((bf16*)Cp + sC * bz + off) = __floats2bfloat162_rn(v0, v1);
                } else {
                    *(float2*)((float*)Cp + sC * bz + off) = make_float2(v0, v1);
                }
            }
            if (EXP) {
                rsum += __shfl_xor_sync(0xFFFFFFFFu, rsum, 1);
                rsum += __shfl_xor_sync(0xFFFFFFFFu, rsum, 2);
                if (c == 0) atomicAdd(&rsums[m], rsum);
            }
        }
    }
}

// Standalone GEMM wrapper (S, PV, proj)
template<bool BIAS_M, bool BIAS_N, bool RES, bool OUTBF, bool EXP, bool DIV>
__global__ __launch_bounds__(128, 2) void gemm_bf(
    const bf16* __restrict__ A, const bf16* __restrict__ Bm, void* __restrict__ Cp,
    const float* __restrict__ bias, const float* __restrict__ R,
    float* __restrict__ rsums,
    int M, int N, int K, int lda, int ldb,
    size_t sA, size_t sB, size_t sC, size_t sR, float alpha)
{
    extern __shared__ char smem[];
    gemm_core<BIAS_M, BIAS_N, RES, OUTBF, EXP, DIV>(
        A, Bm, Cp, bias, R, rsums, M, N, K, lda, ldb, sA, sB, sC, sR, alpha,
        blockIdx.y * BM, blockIdx.x * BN, blockIdx.z, smem);
}

// Merged qk + V launch: blockIdx.y in [0,8) -> qk rows; [8,12) -> V rows.
__global__ __launch_bounds__(128, 2) void qkv_kernel(
    const bf16* __restrict__ hnT, const bf16* __restrict__ wqk,
    const bf16* __restrict__ wv, bf16* __restrict__ qkT, bf16* __restrict__ v,
    const float* __restrict__ bqk, const float* __restrict__ bv,
    size_t sCH, size_t sQK)
{
    extern __shared__ char smem[];
    if (blockIdx.y < 8) {
        gemm_core<false, true, false, true, false, false>(
            hnT, wqk, qkT, bqk, nullptr, nullptr,
            1024, 1024, 512, 512, 512, sCH, 0, sQK, 0, 1.f,
            blockIdx.y * BM, blockIdx.x * BN, blockIdx.z, smem);
    } else {
        gemm_core<true, false, false, true, false, false>(
            wv, hnT, v, bv, nullptr, nullptr,
            512, 1024, 512, 512, 512, 0, sCH, sCH, 0, 1.f,
            (blockIdx.y - 8) * BM, blockIdx.x * BN, blockIdx.z, smem);
    }
}

// ---------------------------------------------------------------------------
// Merged prep: blocks [0,1024): fused GroupNorm (stats+normalize+transpose);
// blocks [1024,2048): weight cvt (+bias pack); blocks [2048,2176): zero rsums.
// ---------------------------------------------------------------------------
#define GN_SMEM (16 * HW * 4)   // 65536 bytes

__global__ __launch_bounds__(256) void prep_kernel(
    const float* __restrict__ x, const float* __restrict__ scale,
    const float* __restrict__ bias, bf16* __restrict__ hnT,
    const float* __restrict__ w0, const float* __restrict__ w1,
    const float* __restrict__ w2, const float* __restrict__ w3,
    const float* __restrict__ bq, const float* __restrict__ bk,
    bf16* __restrict__ wdst, float* __restrict__ bqk, float* __restrict__ rsums)
{
    int bid = blockIdx.x, tid = threadIdx.x;

    if (bid >= 2048) {                       // zero rsums: 128 blocks x 1024 floats
        int i = (bid - 2048) * 256 + tid;
        ((float4*)rsums)[i] = make_float4(0.f, 0.f, 0.f, 0.f);
        return;
    }
    if (bid >= 1024) {                       // weight cvt: 1024 blocks
        int cb = bid - 1024;
        int wy = cb >> 8, wx = cb & 255;
        const float* src = (wy == 0) ? w0 : (wy == 1) ? w1 : (wy == 2) ? w2 : w3;
        bf16* d = wdst + (size_t)wy * C_ * C_;
        int i = wx * 256 + tid;
        float4 vv = *(const float4*)(src + i * 4);
        __nv_bfloat162* d2 = (__nv_bfloat162*)(d + i * 4);
        d2[0] = __floats2bfloat162_rn(vv.x, vv.y);
        d2[1] = __floats2bfloat162_rn(vv.z, vv.w);
        if (wy == 0 && wx < 2) {
            int j = wx * 256 + tid;
            bqk[j] = bq[j]; bqk[j + 512] = bk[j];
        }
        return;
    }

    // fused GroupNorm
    extern __shared__ float xs[];                 // [16][1024]
    __shared__ float red_s[8], red_ss[8];
    __shared__ float a_sh[16], ad_sh[16];

    int lane = tid & 31, warp = tid >> 5;
    int b = bid >> 5, g = bid & 31;
    int c0 = g * 16;
    size_t base = ((size_t)b * C_ + c0) * HW;

    const float4* x4 = (const float4*)(x + base);
    float4* xs4 = (float4*)xs;
    float s = 0.f, ss = 0.f;
    #pragma unroll
    for (int i = tid; i < 4096; i += 256) {
        float4 vv = x4[i];
        xs4[i] = vv;
        s  += vv.x + vv.y + vv.z + vv.w;
        ss += vv.x * vv.x + vv.y * vv.y + vv.z * vv.z + vv.w * vv.w;
    }
    #pragma unroll
    for (int o = 16; o > 0; o >>= 1) {
        s  += __shfl_xor_sync(0xFFFFFFFFu, s, o);
        ss += __shfl_xor_sync(0xFFFFFFFFu, ss, o);
    }
    if (lane == 0) { red_s[warp] = s; red_ss[warp] = ss; }
    __syncthreads();
    if (tid < 16) {
        float ts = 0.f, tss = 0.f;
        #pragma unroll
        for (int w = 0; w < 8; w++) { ts += red_s[w]; tss += red_ss[w]; }
        float mean = ts * (1.f / 16384.f);
        float var  = tss * (1.f / 16384.f) - mean * mean;
        float inv  = rsqrtf(var + EPS);
        float a    = scale[c0 + tid] * inv;
        a_sh[tid]  = a;
        ad_sh[tid] = bias[c0 + tid] - mean * a;
    }
    __syncthreads();

    float a[16], ad[16];
    #pragma unroll
    for (int c = 0; c < 16; c++) { a[c] = a_sh[c]; ad[c] = ad_sh[c]; }

    #pragma unroll
    for (int i = 0; i < 4; i++) {
        int p = tid + i * 256;
        uint32_t pk[8];
        #pragma unroll
        for (int c = 0; c < 8; c++) {
            float v0 = xs[(2 * c + 0) * HW + p] * a[2 * c + 0] + ad[2 * c + 0];
            float v1 = xs[(2 * c + 1) * HW + p] * a[2 * c + 1] + ad[2 * c + 1];
            __nv_bfloat162 h = __floats2bfloat162_rn(v0, v1);
            pk[c] = *(uint32_t*)&h;
        }
        uint4* dst = (uint4*)(hnT + ((size_t)b * HW + p) * C_ + c0);
        dst[0] = make_uint4(pk[0], pk[1], pk[2], pk[3]);
        dst[1] = make_uint4(pk[4], pk[5], pk[6], pk[7]);
    }
}

// ---------------------------------------------------------------------------
extern "C" void kernel_launch(void* const* d_in, const int* in_sizes, int n_in,
                              void* d_out, int out_size)
{
    const float* x  = (const float*)d_in[0];
    const float* gs = (const float*)d_in[1];
    const float* gb = (const float*)d_in[2];
    const float* wq = (const float*)d_in[3];
    const float* bq = (const float*)d_in[4];
    const float* wk = (const float*)d_in[5];
    const float* bk = (const float*)d_in[6];
    const float* wv = (const float*)d_in[7];
    const float* bv = (const float*)d_in[8];
    const float* wp = (const float*)d_in[9];
    const float* bp = (const float*)d_in[10];
    float* out = (float*)d_out;

    bf16 *hnT, *qkT, *v, *oT, *probs, *wb; float *bqk, *rsums;
    cudaGetSymbolAddress((void**)&hnT,   g_hnT);
    cudaGetSymbolAddress((void**)&qkT,   g_qkT);
    cudaGetSymbolAddress((void**)&v,     g_v);
    cudaGetSymbolAddress((void**)&oT,    g_oT);
    cudaGetSymbolAddress((void**)&probs, g_probs);
    cudaGetSymbolAddress((void**)&wb,    g_w);
    cudaGetSymbolAddress((void**)&bqk,   g_bqk);
    cudaGetSymbolAddress((void**)&rsums, g_rowsum);
    bf16 *wvb = wb + 2 * C_ * C_, *wpb = wb + 3 * C_ * C_;

    cudaFuncSetAttribute(prep_kernel, cudaFuncAttributeMaxDynamicSharedMemorySize, GN_SMEM);
    cudaFuncSetAttribute(qkv_kernel,  cudaFuncAttributeMaxDynamicSharedMemorySize, GEMM_SMEM);
    cudaFuncSetAttribute(gemm_bf<false, false, false, true,  true,  false>, cudaFuncAttributeMaxDynamicSharedMemorySize, GEMM_SMEM);
    cudaFuncSetAttribute(gemm_bf<false, false, false, true,  false, true >, cudaFuncAttributeMaxDynamicSharedMemorySize, GEMM_SMEM);
    cudaFuncSetAttribute(gemm_bf<true,  false, true,  false, false, false>, cudaFuncAttributeMaxDynamicSharedMemorySize, GEMM_SMEM);

    const size_t sCH = (size_t)C_ * HW;     // 512*1024
    const size_t sQK = (size_t)HW * 1024;   // qkT batch stride
    const size_t sAA = (size_t)HW * HW;
    const float  scl = 1.f / sqrtf((float)C_);

    // 1) prep: GroupNorm + weight cvt + rsums zero (one launch)
    prep_kernel<<<2176, 256, GN_SMEM>>>(x, gs, gb, hnT,
                                        wq, wk, wv, wp, bq, bk, wb, bqk, rsums);

    // 2) merged qk + V GEMMs (one launch)
    qkv_kernel<<<dim3(8, 12, B_), 128, GEMM_SMEM>>>(hnT, wb, wvb, qkT, v, bqk, bv, sCH, sQK);

    // 3) probs = exp(scl * Q @ K^T) (bf16, unnormalized) + row sums via atomics
    {
        dim3 g(1024 / BN, 1024 / BM, B_);
        gemm_bf<false, false, false, true, true, false><<<g, 128, GEMM_SMEM>>>(
            qkT, qkT + 512, probs, nullptr, nullptr, rsums,
            1024, 1024, 512, 1024, 1024, sQK, sQK, sAA, 0, scl);
    }
    // 4) OT[i,co] = (probs @ V^T) / rowsum[i]   (M=1024, N=512, K=1024)
    {
        dim3 g(512 / BN, 1024 / BM, B_);
        gemm_bf<false, false, false, true, false, true><<<g, 128, GEMM_SMEM>>>(
            probs, v, oT, nullptr, nullptr, rsums,
            1024, 512, 1024, 1024, 1024, sAA, sCH, sCH, 0, 1.f);
    }
    // 5) out[co,p] = wp @ OT^T + bp + x    (M=512, N=1024, K=512) -> fp32 + residual
    {
        dim3 g(1024 / BN, 512 / BM, B_);
        gemm_bf<true, false, true, false, false, false><<<g, 128, GEMM_SMEM>>>(
            wpb, oT, out, bp, x, nullptr,
            512, 1024, 512, 512, 512, 0, sCH, sCH, sCH, 1.f);
    }
}